// round 14
// baseline (speedup 1.0000x reference)
#include <cuda_runtime.h>
#include <cuda_fp16.h>
#include <math.h>
#include <stdint.h>

// ---------------------------------------------------------------------------
// Problem constants
// ---------------------------------------------------------------------------
#define BB 2
#define LL 4096
#define DMOD 1024
#define DI 2048
#define DTR 64
#define KC 4
#define ROWS (BB * LL)       // 8192
#define NCH 64               // scan chunks
#define LC (LL / NCH)        // 64
#define NSPLIT 8             // dtlow split-K factor
#define KSL (DI / NSPLIT)    // 256

// ---------------------------------------------------------------------------
// Scratch (device globals; no allocation allowed)
// ---------------------------------------------------------------------------
__device__ __half g_xzh[(size_t)ROWS * 2 * DI];    // in_proj out (xi | z), f16
__device__ __half g_uh[(size_t)ROWS * DI];         // conv+silu out f16
__device__ float  g_dtp[(size_t)NSPLIT * ROWS * DTR];
__device__ __half g_dtlowh[(size_t)ROWS * DTR];
__device__ __half g_eh[(size_t)ROWS * DI];         // decay factors f16
__device__ __half g_ygh[(size_t)ROWS * DI];        // gated scan out f16
__device__ float  g_S [(size_t)BB * NCH * DI];
__device__ float  g_P [(size_t)BB * NCH * DI];
__device__ float  g_C [(size_t)BB * NCH * DI];
__device__ float  g_Aclip[DI];                     // clip(-exp(A_log))
// fp16 operand copies
__device__ __half g_xh  [(size_t)ROWS * DMOD];
__device__ __half g_inwh[(size_t)2 * DI * DMOD];
__device__ __half g_outwh[(size_t)DMOD * DI];
__device__ __half g_xpwh[(size_t)DTR * DI];
__device__ __half g_dtwh[(size_t)DI * DTR];

// ---------------------------------------------------------------------------
// PTX helpers (generic ISA: cp.async + ldmatrix + mma.sync f16 — sm_103-safe)
// ---------------------------------------------------------------------------
__device__ __forceinline__ uint32_t smem_u32(const void* p) {
    uint32_t a;
    asm("{ .reg .u64 t; cvta.to.shared.u64 t, %1; cvt.u32.u64 %0, t; }"
        : "=r"(a) : "l"(p));
    return a;
}
__device__ __forceinline__ void cp_async16(uint32_t dst, const void* src) {
    asm volatile("cp.async.cg.shared.global [%0], [%1], 16;"
                 :: "r"(dst), "l"(src) : "memory");
}
#define CP_COMMIT() asm volatile("cp.async.commit_group;" ::: "memory")
#define CP_WAIT(n)  asm volatile("cp.async.wait_group %0;" :: "n"(n) : "memory")

__device__ __forceinline__ void ldsm_x4(uint32_t* d, uint32_t addr) {
    asm volatile("ldmatrix.sync.aligned.m8n8.x4.shared.b16 {%0,%1,%2,%3}, [%4];"
                 : "=r"(d[0]), "=r"(d[1]), "=r"(d[2]), "=r"(d[3]) : "r"(addr));
}
__device__ __forceinline__ void mma_f16(float* c, const uint32_t* a, const uint32_t* b) {
    asm volatile(
        "mma.sync.aligned.m16n8k16.row.col.f32.f16.f16.f32 "
        "{%0,%1,%2,%3}, {%4,%5,%6,%7}, {%8,%9}, {%0,%1,%2,%3};"
        : "+f"(c[0]), "+f"(c[1]), "+f"(c[2]), "+f"(c[3])
        : "r"(a[0]), "r"(a[1]), "r"(a[2]), "r"(a[3]), "r"(b[0]), "r"(b[1]));
}

// Fast e-path: A pre-clipped; __expf/__logf intrinsics.
__device__ __forceinline__ float e_from_dpre(float acc, float bias, float A) {
    float v = acc + bias;
    float delta = (v > 20.f) ? v : __logf(1.f + __expf(v));
    delta = fminf(fmaxf(delta, 1e-6f), 10.f);
    float ev = __expf(delta * A);
    return fminf(fmaxf(ev, 1e-6f), 1.f);
}
__device__ __forceinline__ float clip1e4(float v) {
    return fminf(fmaxf(v, -1e4f), 1e4f);
}
__device__ __forceinline__ float fast_silu(float a) {
    return __fdividef(a, 1.f + __expf(-a));
}

// ---------------------------------------------------------------------------
// fp16 tensor-core GEMM (best config): C[M,N] = A[M,K]*B[N,K]^T.
// BM=128, BN template. BK=64 halves. 256 threads, 8 warps (2x4),
// 2-stage cp.async double buffer. SSTH=72 halves -> conflict-free ldmatrix.
// EPI: 0 = f32 store; 2 = fused e-epilogue (half store + smem stash)
//      + scan pass1; 3 = half store to Ch.
// ---------------------------------------------------------------------------
#define SSTH 72
#define BKH  64
#define EST  132   // e-tile smem stride (floats)

template <int BN, int EPI, bool SPLITK>
__global__ __launch_bounds__(256, 2)
void gemm_f16(const __half* __restrict__ A, const __half* __restrict__ B,
              float* __restrict__ C, __half* __restrict__ Ch,
              int M, int N, int Kst, int Ksl,
              const float* __restrict__ vb1, const float* __restrict__ vb2,
              const __half* __restrict__ U,
              float* __restrict__ Sp, float* __restrict__ Pp) {
    constexpr int MT = 4;
    constexpr int NT = BN / 32;
    constexpr int NPAIR = NT / 2;
    constexpr int AF = (128 * 8) / 256;
    constexpr int BF = (BN * 8) / 256;

    extern __shared__ __half smem[];
    const uint32_t sA = smem_u32(smem);
    const uint32_t sB = sA + 2 * 128 * SSTH * 2;

    const int tid = threadIdx.x;
    const int wid = tid >> 5;
    const int lane = tid & 31;
    const int grp = lane >> 2;
    const int qid = lane & 3;
    const int wm = wid >> 2;
    const int wn = wid & 3;

    const int bx = blockIdx.x, by = blockIdx.y;
    const int K = Kst;
    const __half* Ag = A + (size_t)by * 128 * K;
    const __half* Bg = B + (size_t)bx * BN * K;
    if (SPLITK) {
        Ag += (size_t)blockIdx.z * Ksl;
        Bg += (size_t)blockIdx.z * Ksl;
        C  += (size_t)blockIdx.z * M * N;
    }

    const int a_row = lane & 15;
    const int a_kb  = (lane >> 4) * 16;
    const int b_row = ((lane >> 4) << 3) + (lane & 7);
    const int b_kb  = ((lane >> 3) & 1) * 16;

    float acc[MT][NT][4];
    #pragma unroll
    for (int i = 0; i < MT; i++)
        #pragma unroll
        for (int j = 0; j < NT; j++)
            #pragma unroll
            for (int q = 0; q < 4; q++) acc[i][j][q] = 0.f;

    const int nK = Ksl / BKH;

    // prologue: tile 0 -> buf 0
    #pragma unroll
    for (int t = 0; t < AF; t++) {
        int f = tid + t * 256;
        int row = f >> 3, c = f & 7;
        cp_async16(sA + row * 144 + c * 16, Ag + (size_t)row * K + c * 8);
    }
    #pragma unroll
    for (int t = 0; t < BF; t++) {
        int f = tid + t * 256;
        int row = f >> 3, c = f & 7;
        cp_async16(sB + row * 144 + c * 16, Bg + (size_t)row * K + c * 8);
    }
    CP_COMMIT();

    int buf = 0;
    for (int kt = 0; kt < nK; kt++) {
        if (kt + 1 < nK) {
            const uint32_t dA = sA + (buf ^ 1) * 128 * SSTH * 2;
            const uint32_t dB = sB + (buf ^ 1) * BN * SSTH * 2;
            const int koff = (kt + 1) * BKH;
            #pragma unroll
            for (int t = 0; t < AF; t++) {
                int f = tid + t * 256;
                int row = f >> 3, c = f & 7;
                cp_async16(dA + row * 144 + c * 16, Ag + (size_t)row * K + koff + c * 8);
            }
            #pragma unroll
            for (int t = 0; t < BF; t++) {
                int f = tid + t * 256;
                int row = f >> 3, c = f & 7;
                cp_async16(dB + row * 144 + c * 16, Bg + (size_t)row * K + koff + c * 8);
            }
            CP_COMMIT();
            CP_WAIT(1);
        } else {
            CP_WAIT(0);
        }
        __syncthreads();

        const uint32_t Ab = sA + buf * 128 * SSTH * 2;
        const uint32_t Bb = sB + buf * BN * SSTH * 2;

        uint32_t addrA[MT], addrB[NPAIR];
        #pragma unroll
        for (int mt = 0; mt < MT; mt++)
            addrA[mt] = Ab + (wm * 64 + mt * 16 + a_row) * 144 + a_kb;
        #pragma unroll
        for (int p = 0; p < NPAIR; p++)
            addrB[p] = Bb + (wn * (NT * 8) + p * 16 + b_row) * 144 + b_kb;

        #pragma unroll
        for (int s = 0; s < BKH / 16; s++) {
            uint32_t af[MT][4];
            #pragma unroll
            for (int mt = 0; mt < MT; mt++)
                ldsm_x4(af[mt], addrA[mt] + s * 32);
            uint32_t bf[NPAIR][4];
            #pragma unroll
            for (int p = 0; p < NPAIR; p++)
                ldsm_x4(bf[p], addrB[p] + s * 32);
            #pragma unroll
            for (int mt = 0; mt < MT; mt++)
                #pragma unroll
                for (int nt = 0; nt < NT; nt++)
                    mma_f16(acc[mt][nt], af[mt], &bf[nt >> 1][(nt & 1) * 2]);
        }
        __syncthreads();
        buf ^= 1;
    }

    float* se = (float*)smem;   // e-tile stash for EPI==2

    // epilogue
    #pragma unroll
    for (int mt = 0; mt < MT; mt++) {
        const int rl = wm * 64 + mt * 16 + grp;
        const int r0 = by * 128 + rl;
        #pragma unroll
        for (int nt = 0; nt < NT; nt++) {
            const int cl = wn * (NT * 8) + nt * 8 + qid * 2;
            const int c0 = bx * BN + cl;
            float o0 = acc[mt][nt][0], o1 = acc[mt][nt][1];
            float o2 = acc[mt][nt][2], o3 = acc[mt][nt][3];
            if (EPI == 2) {
                float2 bb = *(const float2*)(vb1 + c0);
                float2 aa = *(const float2*)(vb2 + c0);   // pre-clipped A
                o0 = e_from_dpre(o0, bb.x, aa.x); o1 = e_from_dpre(o1, bb.y, aa.y);
                o2 = e_from_dpre(o2, bb.x, aa.x); o3 = e_from_dpre(o3, bb.y, aa.y);
                *(float2*)(se + rl * EST + cl) = make_float2(o0, o1);
                *(float2*)(se + (rl + 8) * EST + cl) = make_float2(o2, o3);
                *(__half2*)(Ch + (size_t)r0 * N + c0) = __floats2half2_rn(o0, o1);
                *(__half2*)(Ch + (size_t)(r0 + 8) * N + c0) = __floats2half2_rn(o2, o3);
            } else if (EPI == 3) {
                *(__half2*)(Ch + (size_t)r0 * N + c0) = __floats2half2_rn(o0, o1);
                *(__half2*)(Ch + (size_t)(r0 + 8) * N + c0) = __floats2half2_rn(o2, o3);
            } else {
                *(float2*)(C + (size_t)r0 * N + c0) = make_float2(o0, o1);
                *(float2*)(C + (size_t)(r0 + 8) * N + c0) = make_float2(o2, o3);
            }
        }
    }

    if (EPI == 2) {
        // fused scan pass1: 2 chunks x 128 d per block, one thread each.
        __syncthreads();
        const int ci = tid >> 7;
        const int dl = tid & 127;
        const size_t row0 = (size_t)by * 128 + ci * 64;
        const int b = (int)(row0 >> 12);
        const int c = (int)((row0 & 4095) >> 6);
        const int d = bx * BN + dl;
        const __half* up = U + row0 * N + d;
        const float* ep = se + ci * 64 * EST + dl;
        float st = 0.f, pr = 1.f;
        #pragma unroll 8
        for (int l = 0; l < LC; l++) {
            float et = ep[l * EST];
            float ut = __half2float(up[(size_t)l * N]);
            st = clip1e4(fmaf(st, et, ut));
            pr *= et;
        }
        const size_t gi = ((size_t)b * NCH + c) * DI + d;
        Sp[gi] = st;
        Pp[gi] = pr;
    }
}

// ---------------------------------------------------------------------------
// Batched prepass: f32 -> f16 conversions + Aclip precompute.
// ---------------------------------------------------------------------------
#define N8_X    (ROWS * DMOD / 8)
#define N8_INW  (2 * DI * DMOD / 8)
#define N8_OUTW (DMOD * DI / 8)
#define N8_XPW  (DTR * DI / 8)
#define N8_DTW  (DI * DTR / 8)
#define N8_ACL  (DI / 8)
#define N8_TOT  (N8_X + N8_INW + N8_OUTW + N8_XPW + N8_DTW + N8_ACL)

__device__ __forceinline__ void cvt8(const float* in, __half* out, int i) {
    float4 v0 = ((const float4*)in)[2 * i];
    float4 v1 = ((const float4*)in)[2 * i + 1];
    __half2 h0 = __floats2half2_rn(v0.x, v0.y);
    __half2 h1 = __floats2half2_rn(v0.z, v0.w);
    __half2 h2 = __floats2half2_rn(v1.x, v1.y);
    __half2 h3 = __floats2half2_rn(v1.z, v1.w);
    uint4 o;
    o.x = *(uint32_t*)&h0; o.y = *(uint32_t*)&h1;
    o.z = *(uint32_t*)&h2; o.w = *(uint32_t*)&h3;
    ((uint4*)out)[i] = o;
}

__global__ __launch_bounds__(256)
void prep_all_kernel(const float* x, __half* xh,
                     const float* inw, __half* inwh,
                     const float* outw, __half* outwh,
                     const float* xpw, __half* xpwh,
                     const float* dtw, __half* dtwh,
                     const float* alog, float* Aclip) {
    int i = blockIdx.x * blockDim.x + threadIdx.x;
    if (i < N8_X) { cvt8(x, xh, i); return; }
    i -= N8_X;
    if (i < N8_INW) { cvt8(inw, inwh, i); return; }
    i -= N8_INW;
    if (i < N8_OUTW) { cvt8(outw, outwh, i); return; }
    i -= N8_OUTW;
    if (i < N8_XPW) { cvt8(xpw, xpwh, i); return; }
    i -= N8_XPW;
    if (i < N8_DTW) { cvt8(dtw, dtwh, i); return; }
    i -= N8_DTW;
    if (i < N8_ACL) {
        #pragma unroll
        for (int j = 0; j < 8; j++) {
            int d = i * 8 + j;
            Aclip[d] = fminf(fmaxf(-expf(alog[d]), -10.f), -1e-6f);
        }
    }
}

// ---------------------------------------------------------------------------
// dtlow split-K reduce: sum NSPLIT f32 partials -> half. 8 float4 per thread.
// ---------------------------------------------------------------------------
__global__ __launch_bounds__(256)
void dtred_kernel(const float* __restrict__ dtp, __half* __restrict__ dtlowh) {
    int i = blockIdx.x * blockDim.x + threadIdx.x;     // < ROWS*DTR/4
    const int STRIDE4 = ROWS * DTR / 4;
    float4 s = ((const float4*)dtp)[i];
    #pragma unroll
    for (int p = 1; p < NSPLIT; p++) {
        float4 v = ((const float4*)dtp)[i + p * STRIDE4];
        s.x += v.x; s.y += v.y; s.z += v.z; s.w += v.w;
    }
    __half2 lo = __floats2half2_rn(s.x, s.y);
    __half2 hi = __floats2half2_rn(s.z, s.w);
    uint2 o; o.x = *(uint32_t*)&lo; o.y = *(uint32_t*)&hi;
    ((uint2*)dtlowh)[i] = o;
}

// ---------------------------------------------------------------------------
// half4 helpers
// ---------------------------------------------------------------------------
__device__ __forceinline__ void store_half4(__half* p, float4 v) {
    __half2 lo = __floats2half2_rn(v.x, v.y);
    __half2 hi = __floats2half2_rn(v.z, v.w);
    uint2 o; o.x = *(uint32_t*)&lo; o.y = *(uint32_t*)&hi;
    *(uint2*)p = o;
}
__device__ __forceinline__ float4 load_half4(const __half* p) {
    uint2 v = *(const uint2*)p;
    float2 f0 = __half22float2(*(__half2*)&v.x);
    float2 f1 = __half22float2(*(__half2*)&v.y);
    return make_float4(f0.x, f0.y, f1.x, f1.y);
}
__device__ __forceinline__ float4 silu4(float4 a) {
    a.x = fast_silu(a.x);
    a.y = fast_silu(a.y);
    a.z = fast_silu(a.z);
    a.w = fast_silu(a.w);
    return a;
}
__device__ __forceinline__ float4 fma4(float4 a, float4 b, float4 c) {
    return make_float4(fmaf(a.x, b.x, c.x), fmaf(a.y, b.y, c.y),
                       fmaf(a.z, b.z, c.z), fmaf(a.w, b.w, c.w));
}

// ---------------------------------------------------------------------------
// Depthwise causal conv1d + bias + SiLU. half in, half out. 16 l per thread.
// ---------------------------------------------------------------------------
__global__ __launch_bounds__(256)
void conv_silu_kernel(const __half* __restrict__ xzh,
                      const float* __restrict__ cw,
                      const float* __restrict__ cb,
                      __half* __restrict__ uh) {
    int idx = blockIdx.x * blockDim.x + threadIdx.x;   // (ROWS/16)*(DI/4)
    int dq = idx & (DI / 4 - 1);
    int g = idx >> 9;
    int l0 = (g & (LL / 16 - 1)) * 16;
    int b = g >> 8;
    size_t bl0 = (size_t)b * LL + l0;
    const int d = dq * 4;

    float4 r0 = *(const float4*)(cw + (d + 0) * KC);
    float4 r1 = *(const float4*)(cw + (d + 1) * KC);
    float4 r2 = *(const float4*)(cw + (d + 2) * KC);
    float4 r3 = *(const float4*)(cw + (d + 3) * KC);
    float4 w0 = make_float4(r0.x, r1.x, r2.x, r3.x);
    float4 w1 = make_float4(r0.y, r1.y, r2.y, r3.y);
    float4 w2 = make_float4(r0.z, r1.z, r2.z, r3.z);
    float4 w3 = make_float4(r0.w, r1.w, r2.w, r3.w);
    float4 bias = *(const float4*)(cb + d);

    float4 xm3 = make_float4(0, 0, 0, 0), xm2 = xm3, xm1 = xm3;
    if (l0 > 0) {
        xm3 = load_half4(xzh + (bl0 - 3) * (2 * DI) + d);
        xm2 = load_half4(xzh + (bl0 - 2) * (2 * DI) + d);
        xm1 = load_half4(xzh + (bl0 - 1) * (2 * DI) + d);
    }
    #pragma unroll
    for (int j = 0; j < 16; j++) {
        float4 xc = load_half4(xzh + (bl0 + j) * (2 * DI) + d);
        float4 acc = bias;
        acc = fma4(w0, xm3, acc);
        acc = fma4(w1, xm2, acc);
        acc = fma4(w2, xm1, acc);
        acc = fma4(w3, xc, acc);
        store_half4(uh + (bl0 + j) * DI + d, silu4(acc));
        xm3 = xm2; xm2 = xm1; xm1 = xc;
    }
}

// ---------------------------------------------------------------------------
// Warp-parallel carry scan: one warp per (b, d) channel, 2 chunks per lane.
// ---------------------------------------------------------------------------
__global__ __launch_bounds__(256)
void carry_kernel(const float* __restrict__ S, const float* __restrict__ P,
                  float* __restrict__ Cy) {
    const int gw = (blockIdx.x * blockDim.x + threadIdx.x) >> 5;  // < BB*DI
    const int lane = threadIdx.x & 31;
    const int b = gw / DI;
    const int d = gw - b * DI;

    const int c0 = 2 * lane;
    const size_t i0 = ((size_t)b * NCH + c0) * DI + d;
    const size_t i1 = i0 + DI;

    float p0 = P[i0], s0 = S[i0];
    float p1 = P[i1], s1 = S[i1];

    float lp = p0 * p1;
    float ls = fmaf(s0, p1, s1);

    #pragma unroll
    for (int off = 1; off < 32; off <<= 1) {
        float pp = __shfl_up_sync(0xFFFFFFFFu, lp, off);
        float ss = __shfl_up_sync(0xFFFFFFFFu, ls, off);
        if (lane >= off) {
            ls = fmaf(ss, lp, ls);
            lp = pp * lp;
        }
    }

    float prev_s = __shfl_up_sync(0xFFFFFFFFu, ls, 1);
    if (lane == 0) prev_s = 0.f;
    Cy[i0] = clip1e4(prev_s);
    Cy[i1] = clip1e4(fmaf(prev_s, p0, s0));
}

// ---------------------------------------------------------------------------
// Scan pass2 (e f16, fast silu gate)
// ---------------------------------------------------------------------------
__global__ __launch_bounds__(256)
void scan_pass2(const __half* __restrict__ eh, const __half* __restrict__ uh,
                const __half* __restrict__ xzh, const float* __restrict__ Dvec,
                const float* __restrict__ Cy, __half* __restrict__ ygh) {
    int gid = blockIdx.x * blockDim.x + threadIdx.x;
    int dq = gid & (DI / 4 - 1);
    int bc = gid / (DI / 4);
    int c = bc & (NCH - 1);
    int b = bc / NCH;
    size_t base  = ((size_t)b * LL + (size_t)c * LC) * DI + dq * 4;
    size_t zbase = ((size_t)b * LL + (size_t)c * LC) * (2 * DI) + DI + dq * 4;
    float4 Dd = *(const float4*)(Dvec + dq * 4);
    float4 st = ((const float4*)Cy)[gid];
    #pragma unroll 4
    for (int l = 0; l < LC; l++) {
        float4 et = load_half4(eh + base + (size_t)l * DI);
        float4 ut = load_half4(uh + base + (size_t)l * DI);
        float4 zt = load_half4(xzh + zbase + (size_t)l * (2 * DI));
        st.x = clip1e4(fmaf(st.x, et.x, ut.x));
        st.y = clip1e4(fmaf(st.y, et.y, ut.y));
        st.z = clip1e4(fmaf(st.z, et.z, ut.z));
        st.w = clip1e4(fmaf(st.w, et.w, ut.w));
        float4 o;
        o.x = clip1e4(fmaf(ut.x, Dd.x, st.x)) * fast_silu(zt.x);
        o.y = clip1e4(fmaf(ut.y, Dd.y, st.y)) * fast_silu(zt.y);
        o.z = clip1e4(fmaf(ut.z, Dd.z, st.z)) * fast_silu(zt.z);
        o.w = clip1e4(fmaf(ut.w, Dd.w, st.w)) * fast_silu(zt.w);
        store_half4(ygh + base + (size_t)l * DI, o);
    }
}

// ---------------------------------------------------------------------------
// Launch
// ---------------------------------------------------------------------------
extern "C" void kernel_launch(void* const* d_in, const int* in_sizes, int n_in,
                              void* d_out, int out_size) {
    const float* x     = (const float*)d_in[0];
    const float* inw   = (const float*)d_in[1];
    const float* convw = (const float*)d_in[2];
    const float* convb = (const float*)d_in[3];
    const float* xpw   = (const float*)d_in[4];
    const float* dtw   = (const float*)d_in[5];
    const float* dtb   = (const float*)d_in[6];
    const float* alog  = (const float*)d_in[7];
    const float* Dvec  = (const float*)d_in[8];
    const float* outw  = (const float*)d_in[9];
    float* out = (float*)d_out;

    float *S, *P, *Cy, *dtp, *Aclip;
    __half *xzh, *uh, *dtlowh, *eh, *ygh, *xh, *inwh, *outwh, *xpwh, *dtwh;
    cudaGetSymbolAddress((void**)&xzh, g_xzh);
    cudaGetSymbolAddress((void**)&uh, g_uh);
    cudaGetSymbolAddress((void**)&dtp, g_dtp);
    cudaGetSymbolAddress((void**)&dtlowh, g_dtlowh);
    cudaGetSymbolAddress((void**)&eh, g_eh);
    cudaGetSymbolAddress((void**)&ygh, g_ygh);
    cudaGetSymbolAddress((void**)&S, g_S);
    cudaGetSymbolAddress((void**)&P, g_P);
    cudaGetSymbolAddress((void**)&Cy, g_C);
    cudaGetSymbolAddress((void**)&Aclip, g_Aclip);
    cudaGetSymbolAddress((void**)&xh, g_xh);
    cudaGetSymbolAddress((void**)&inwh, g_inwh);
    cudaGetSymbolAddress((void**)&outwh, g_outwh);
    cudaGetSymbolAddress((void**)&xpwh, g_xpwh);
    cudaGetSymbolAddress((void**)&dtwh, g_dtwh);

    const int SM128 = 2 * (128 * SSTH + 128 * SSTH) * 2;   // 73728 B
    const int SM64  = 2 * (128 * SSTH + 64 * SSTH) * 2;    // 55296 B
    cudaFuncSetAttribute((const void*)gemm_f16<128, 0, false>,
                         cudaFuncAttributeMaxDynamicSharedMemorySize, SM128);
    cudaFuncSetAttribute((const void*)gemm_f16<128, 2, false>,
                         cudaFuncAttributeMaxDynamicSharedMemorySize, SM128);
    cudaFuncSetAttribute((const void*)gemm_f16<128, 3, false>,
                         cudaFuncAttributeMaxDynamicSharedMemorySize, SM128);
    cudaFuncSetAttribute((const void*)gemm_f16<64, 0, true>,
                         cudaFuncAttributeMaxDynamicSharedMemorySize, SM64);

    // 0. batched prepass (conversions + Aclip)
    prep_all_kernel<<<(N8_TOT + 255) / 256, 256>>>(
        x, xh, inw, inwh, outw, outwh, xpw, xpwh, dtw, dtwh, alog, Aclip);

    // 1. in_proj: xzh[8192,4096] = xh * inwh^T (K=1024), half output
    gemm_f16<128, 3, false><<<dim3((2 * DI) / 128, ROWS / 128), 256, SM128>>>(
        xh, inwh, nullptr, xzh, ROWS, 2 * DI, DMOD, DMOD,
        nullptr, nullptr, nullptr, nullptr, nullptr);
    // 2. conv + silu -> uh
    conv_silu_kernel<<<(ROWS / 16) * (DI / 4) / 256, 256>>>(xzh, convw, convb, uh);
    // 3. dtlow split-K (x8) + reduce
    gemm_f16<64, 0, true><<<dim3(1, ROWS / 128, NSPLIT), 256, SM64>>>(
        uh, xpwh, dtp, nullptr, ROWS, DTR, DI, KSL,
        nullptr, nullptr, nullptr, nullptr, nullptr);
    dtred_kernel<<<(ROWS * DTR / 4) / 256, 256>>>(dtp, dtlowh);
    // 4. e = f(dtlowh * dtwh^T + dtb) (K=64, half out) + fused pass1 -> S, P
    gemm_f16<128, 2, false><<<dim3(DI / 128, ROWS / 128), 256, SM128>>>(
        dtlowh, dtwh, nullptr, eh, ROWS, DI, DTR, DTR,
        dtb, Aclip, uh, S, P);
    // 5. warp-parallel carry + scan pass2
    carry_kernel<<<(BB * DI * 32) / 256, 256>>>(S, P, Cy);
    scan_pass2<<<(BB * NCH * DI / 4) / 256, 256>>>(eh, uh, xzh, Dvec, Cy, ygh);
    // 6. out_proj: out[8192,1024] = ygh * outwh^T (K=2048), f32 output
    gemm_f16<128, 0, false><<<dim3(DMOD / 128, ROWS / 128), 256, SM128>>>(
        ygh, outwh, out, nullptr, ROWS, DMOD, DI, DI,
        nullptr, nullptr, nullptr, nullptr, nullptr);
}

// round 15
// speedup vs baseline: 1.0032x; 1.0032x over previous
#include <cuda_runtime.h>
#include <cuda_fp16.h>
#include <math.h>
#include <stdint.h>

// ---------------------------------------------------------------------------
// Problem constants
// ---------------------------------------------------------------------------
#define BB 2
#define LL 4096
#define DMOD 1024
#define DI 2048
#define DTR 64
#define KC 4
#define ROWS (BB * LL)       // 8192
#define NCH 64               // scan chunks
#define LC (LL / NCH)        // 64
#define NSPLIT 4             // dtlow split-K factor (R13 optimum; 8 regressed)
#define KSL (DI / NSPLIT)    // 512

// ---------------------------------------------------------------------------
// Scratch (device globals; no allocation allowed)
// ---------------------------------------------------------------------------
__device__ __half g_xzh[(size_t)ROWS * 2 * DI];    // in_proj out (xi | z), f16
__device__ __half g_uh[(size_t)ROWS * DI];         // conv+silu out f16
__device__ float  g_dtp[(size_t)NSPLIT * ROWS * DTR];
__device__ __half g_dtlowh[(size_t)ROWS * DTR];
__device__ __half g_eh[(size_t)ROWS * DI];         // decay factors f16
__device__ __half g_ygh[(size_t)ROWS * DI];        // gated scan out f16
__device__ float  g_S [(size_t)BB * NCH * DI];
__device__ float  g_P [(size_t)BB * NCH * DI];
__device__ float  g_C [(size_t)BB * NCH * DI];
__device__ float  g_Aclip[DI];                     // clip(-exp(A_log))
// fp16 operand copies
__device__ __half g_xh  [(size_t)ROWS * DMOD];
__device__ __half g_inwh[(size_t)2 * DI * DMOD];
__device__ __half g_outwh[(size_t)DMOD * DI];
__device__ __half g_xpwh[(size_t)DTR * DI];
__device__ __half g_dtwh[(size_t)DI * DTR];

// ---------------------------------------------------------------------------
// PTX helpers (generic ISA: cp.async + ldmatrix + mma.sync f16 — sm_103-safe)
// ---------------------------------------------------------------------------
__device__ __forceinline__ uint32_t smem_u32(const void* p) {
    uint32_t a;
    asm("{ .reg .u64 t; cvta.to.shared.u64 t, %1; cvt.u32.u64 %0, t; }"
        : "=r"(a) : "l"(p));
    return a;
}
__device__ __forceinline__ void cp_async16(uint32_t dst, const void* src) {
    asm volatile("cp.async.cg.shared.global [%0], [%1], 16;"
                 :: "r"(dst), "l"(src) : "memory");
}
#define CP_COMMIT() asm volatile("cp.async.commit_group;" ::: "memory")
#define CP_WAIT(n)  asm volatile("cp.async.wait_group %0;" :: "n"(n) : "memory")

__device__ __forceinline__ void ldsm_x4(uint32_t* d, uint32_t addr) {
    asm volatile("ldmatrix.sync.aligned.m8n8.x4.shared.b16 {%0,%1,%2,%3}, [%4];"
                 : "=r"(d[0]), "=r"(d[1]), "=r"(d[2]), "=r"(d[3]) : "r"(addr));
}
__device__ __forceinline__ void mma_f16(float* c, const uint32_t* a, const uint32_t* b) {
    asm volatile(
        "mma.sync.aligned.m16n8k16.row.col.f32.f16.f16.f32 "
        "{%0,%1,%2,%3}, {%4,%5,%6,%7}, {%8,%9}, {%0,%1,%2,%3};"
        : "+f"(c[0]), "+f"(c[1]), "+f"(c[2]), "+f"(c[3])
        : "r"(a[0]), "r"(a[1]), "r"(a[2]), "r"(a[3]), "r"(b[0]), "r"(b[1]));
}

// Fast e-path: A pre-clipped; __expf/__logf intrinsics.
__device__ __forceinline__ float e_from_dpre(float acc, float bias, float A) {
    float v = acc + bias;
    float delta = (v > 20.f) ? v : __logf(1.f + __expf(v));
    delta = fminf(fmaxf(delta, 1e-6f), 10.f);
    float ev = __expf(delta * A);
    return fminf(fmaxf(ev, 1e-6f), 1.f);
}
__device__ __forceinline__ float clip1e4(float v) {
    return fminf(fmaxf(v, -1e4f), 1e4f);
}
__device__ __forceinline__ float fast_silu(float a) {
    return __fdividef(a, 1.f + __expf(-a));
}

// ---------------------------------------------------------------------------
// fp16 tensor-core GEMM (best config): C[M,N] = A[M,K]*B[N,K]^T.
// BM=128, BN template. BK=64 halves. 256 threads, 8 warps (2x4),
// 2-stage cp.async double buffer. SSTH=72 halves -> conflict-free ldmatrix.
// EPI: 0 = f32 store; 2 = fused e-epilogue (half store + smem stash)
//      + scan pass1; 3 = half store to Ch.
// ---------------------------------------------------------------------------
#define SSTH 72
#define BKH  64
#define EST  132   // e-tile smem stride (floats)

template <int BN, int EPI, bool SPLITK>
__global__ __launch_bounds__(256, 2)
void gemm_f16(const __half* __restrict__ A, const __half* __restrict__ B,
              float* __restrict__ C, __half* __restrict__ Ch,
              int M, int N, int Kst, int Ksl,
              const float* __restrict__ vb1, const float* __restrict__ vb2,
              const __half* __restrict__ U,
              float* __restrict__ Sp, float* __restrict__ Pp) {
    constexpr int MT = 4;
    constexpr int NT = BN / 32;
    constexpr int NPAIR = NT / 2;
    constexpr int AF = (128 * 8) / 256;
    constexpr int BF = (BN * 8) / 256;

    extern __shared__ __half smem[];
    const uint32_t sA = smem_u32(smem);
    const uint32_t sB = sA + 2 * 128 * SSTH * 2;

    const int tid = threadIdx.x;
    const int wid = tid >> 5;
    const int lane = tid & 31;
    const int grp = lane >> 2;
    const int qid = lane & 3;
    const int wm = wid >> 2;
    const int wn = wid & 3;

    const int bx = blockIdx.x, by = blockIdx.y;
    const int K = Kst;
    const __half* Ag = A + (size_t)by * 128 * K;
    const __half* Bg = B + (size_t)bx * BN * K;
    if (SPLITK) {
        Ag += (size_t)blockIdx.z * Ksl;
        Bg += (size_t)blockIdx.z * Ksl;
        C  += (size_t)blockIdx.z * M * N;
    }

    const int a_row = lane & 15;
    const int a_kb  = (lane >> 4) * 16;
    const int b_row = ((lane >> 4) << 3) + (lane & 7);
    const int b_kb  = ((lane >> 3) & 1) * 16;

    float acc[MT][NT][4];
    #pragma unroll
    for (int i = 0; i < MT; i++)
        #pragma unroll
        for (int j = 0; j < NT; j++)
            #pragma unroll
            for (int q = 0; q < 4; q++) acc[i][j][q] = 0.f;

    const int nK = Ksl / BKH;

    // prologue: tile 0 -> buf 0
    #pragma unroll
    for (int t = 0; t < AF; t++) {
        int f = tid + t * 256;
        int row = f >> 3, c = f & 7;
        cp_async16(sA + row * 144 + c * 16, Ag + (size_t)row * K + c * 8);
    }
    #pragma unroll
    for (int t = 0; t < BF; t++) {
        int f = tid + t * 256;
        int row = f >> 3, c = f & 7;
        cp_async16(sB + row * 144 + c * 16, Bg + (size_t)row * K + c * 8);
    }
    CP_COMMIT();

    int buf = 0;
    for (int kt = 0; kt < nK; kt++) {
        if (kt + 1 < nK) {
            const uint32_t dA = sA + (buf ^ 1) * 128 * SSTH * 2;
            const uint32_t dB = sB + (buf ^ 1) * BN * SSTH * 2;
            const int koff = (kt + 1) * BKH;
            #pragma unroll
            for (int t = 0; t < AF; t++) {
                int f = tid + t * 256;
                int row = f >> 3, c = f & 7;
                cp_async16(dA + row * 144 + c * 16, Ag + (size_t)row * K + koff + c * 8);
            }
            #pragma unroll
            for (int t = 0; t < BF; t++) {
                int f = tid + t * 256;
                int row = f >> 3, c = f & 7;
                cp_async16(dB + row * 144 + c * 16, Bg + (size_t)row * K + koff + c * 8);
            }
            CP_COMMIT();
            CP_WAIT(1);
        } else {
            CP_WAIT(0);
        }
        __syncthreads();

        const uint32_t Ab = sA + buf * 128 * SSTH * 2;
        const uint32_t Bb = sB + buf * BN * SSTH * 2;

        uint32_t addrA[MT], addrB[NPAIR];
        #pragma unroll
        for (int mt = 0; mt < MT; mt++)
            addrA[mt] = Ab + (wm * 64 + mt * 16 + a_row) * 144 + a_kb;
        #pragma unroll
        for (int p = 0; p < NPAIR; p++)
            addrB[p] = Bb + (wn * (NT * 8) + p * 16 + b_row) * 144 + b_kb;

        #pragma unroll
        for (int s = 0; s < BKH / 16; s++) {
            uint32_t af[MT][4];
            #pragma unroll
            for (int mt = 0; mt < MT; mt++)
                ldsm_x4(af[mt], addrA[mt] + s * 32);
            uint32_t bf[NPAIR][4];
            #pragma unroll
            for (int p = 0; p < NPAIR; p++)
                ldsm_x4(bf[p], addrB[p] + s * 32);
            #pragma unroll
            for (int mt = 0; mt < MT; mt++)
                #pragma unroll
                for (int nt = 0; nt < NT; nt++)
                    mma_f16(acc[mt][nt], af[mt], &bf[nt >> 1][(nt & 1) * 2]);
        }
        __syncthreads();
        buf ^= 1;
    }

    float* se = (float*)smem;   // e-tile stash for EPI==2

    // epilogue
    #pragma unroll
    for (int mt = 0; mt < MT; mt++) {
        const int rl = wm * 64 + mt * 16 + grp;
        const int r0 = by * 128 + rl;
        #pragma unroll
        for (int nt = 0; nt < NT; nt++) {
            const int cl = wn * (NT * 8) + nt * 8 + qid * 2;
            const int c0 = bx * BN + cl;
            float o0 = acc[mt][nt][0], o1 = acc[mt][nt][1];
            float o2 = acc[mt][nt][2], o3 = acc[mt][nt][3];
            if (EPI == 2) {
                float2 bb = *(const float2*)(vb1 + c0);
                float2 aa = *(const float2*)(vb2 + c0);   // pre-clipped A
                o0 = e_from_dpre(o0, bb.x, aa.x); o1 = e_from_dpre(o1, bb.y, aa.y);
                o2 = e_from_dpre(o2, bb.x, aa.x); o3 = e_from_dpre(o3, bb.y, aa.y);
                *(float2*)(se + rl * EST + cl) = make_float2(o0, o1);
                *(float2*)(se + (rl + 8) * EST + cl) = make_float2(o2, o3);
                *(__half2*)(Ch + (size_t)r0 * N + c0) = __floats2half2_rn(o0, o1);
                *(__half2*)(Ch + (size_t)(r0 + 8) * N + c0) = __floats2half2_rn(o2, o3);
            } else if (EPI == 3) {
                *(__half2*)(Ch + (size_t)r0 * N + c0) = __floats2half2_rn(o0, o1);
                *(__half2*)(Ch + (size_t)(r0 + 8) * N + c0) = __floats2half2_rn(o2, o3);
            } else {
                *(float2*)(C + (size_t)r0 * N + c0) = make_float2(o0, o1);
                *(float2*)(C + (size_t)(r0 + 8) * N + c0) = make_float2(o2, o3);
            }
        }
    }

    if (EPI == 2) {
        // fused scan pass1: 2 chunks x 128 d per block, one thread each.
        __syncthreads();
        const int ci = tid >> 7;
        const int dl = tid & 127;
        const size_t row0 = (size_t)by * 128 + ci * 64;
        const int b = (int)(row0 >> 12);
        const int c = (int)((row0 & 4095) >> 6);
        const int d = bx * BN + dl;
        const __half* up = U + row0 * N + d;
        const float* ep = se + ci * 64 * EST + dl;
        float st = 0.f, pr = 1.f;
        #pragma unroll 8
        for (int l = 0; l < LC; l++) {
            float et = ep[l * EST];
            float ut = __half2float(up[(size_t)l * N]);
            st = clip1e4(fmaf(st, et, ut));
            pr *= et;
        }
        const size_t gi = ((size_t)b * NCH + c) * DI + d;
        Sp[gi] = st;
        Pp[gi] = pr;
    }
}

// ---------------------------------------------------------------------------
// Batched prepass: f32 -> f16 conversions + Aclip precompute.
// ---------------------------------------------------------------------------
#define N8_X    (ROWS * DMOD / 8)
#define N8_INW  (2 * DI * DMOD / 8)
#define N8_OUTW (DMOD * DI / 8)
#define N8_XPW  (DTR * DI / 8)
#define N8_DTW  (DI * DTR / 8)
#define N8_ACL  (DI / 8)
#define N8_TOT  (N8_X + N8_INW + N8_OUTW + N8_XPW + N8_DTW + N8_ACL)

__device__ __forceinline__ void cvt8(const float* in, __half* out, int i) {
    float4 v0 = ((const float4*)in)[2 * i];
    float4 v1 = ((const float4*)in)[2 * i + 1];
    __half2 h0 = __floats2half2_rn(v0.x, v0.y);
    __half2 h1 = __floats2half2_rn(v0.z, v0.w);
    __half2 h2 = __floats2half2_rn(v1.x, v1.y);
    __half2 h3 = __floats2half2_rn(v1.z, v1.w);
    uint4 o;
    o.x = *(uint32_t*)&h0; o.y = *(uint32_t*)&h1;
    o.z = *(uint32_t*)&h2; o.w = *(uint32_t*)&h3;
    ((uint4*)out)[i] = o;
}

__global__ __launch_bounds__(256)
void prep_all_kernel(const float* x, __half* xh,
                     const float* inw, __half* inwh,
                     const float* outw, __half* outwh,
                     const float* xpw, __half* xpwh,
                     const float* dtw, __half* dtwh,
                     const float* alog, float* Aclip) {
    int i = blockIdx.x * blockDim.x + threadIdx.x;
    if (i < N8_X) { cvt8(x, xh, i); return; }
    i -= N8_X;
    if (i < N8_INW) { cvt8(inw, inwh, i); return; }
    i -= N8_INW;
    if (i < N8_OUTW) { cvt8(outw, outwh, i); return; }
    i -= N8_OUTW;
    if (i < N8_XPW) { cvt8(xpw, xpwh, i); return; }
    i -= N8_XPW;
    if (i < N8_DTW) { cvt8(dtw, dtwh, i); return; }
    i -= N8_DTW;
    if (i < N8_ACL) {
        #pragma unroll
        for (int j = 0; j < 8; j++) {
            int d = i * 8 + j;
            Aclip[d] = fminf(fmaxf(-expf(alog[d]), -10.f), -1e-6f);
        }
    }
}

// ---------------------------------------------------------------------------
// dtlow split-K reduce: sum NSPLIT f32 partials -> half.
// ---------------------------------------------------------------------------
__global__ __launch_bounds__(256)
void dtred_kernel(const float* __restrict__ dtp, __half* __restrict__ dtlowh) {
    int i = blockIdx.x * blockDim.x + threadIdx.x;     // < ROWS*DTR/4
    const int STRIDE4 = ROWS * DTR / 4;
    float4 s = ((const float4*)dtp)[i];
    #pragma unroll
    for (int p = 1; p < NSPLIT; p++) {
        float4 v = ((const float4*)dtp)[i + p * STRIDE4];
        s.x += v.x; s.y += v.y; s.z += v.z; s.w += v.w;
    }
    __half2 lo = __floats2half2_rn(s.x, s.y);
    __half2 hi = __floats2half2_rn(s.z, s.w);
    uint2 o; o.x = *(uint32_t*)&lo; o.y = *(uint32_t*)&hi;
    ((uint2*)dtlowh)[i] = o;
}

// ---------------------------------------------------------------------------
// half4 helpers
// ---------------------------------------------------------------------------
__device__ __forceinline__ void store_half4(__half* p, float4 v) {
    __half2 lo = __floats2half2_rn(v.x, v.y);
    __half2 hi = __floats2half2_rn(v.z, v.w);
    uint2 o; o.x = *(uint32_t*)&lo; o.y = *(uint32_t*)&hi;
    *(uint2*)p = o;
}
__device__ __forceinline__ float4 load_half4(const __half* p) {
    uint2 v = *(const uint2*)p;
    float2 f0 = __half22float2(*(__half2*)&v.x);
    float2 f1 = __half22float2(*(__half2*)&v.y);
    return make_float4(f0.x, f0.y, f1.x, f1.y);
}
__device__ __forceinline__ float4 silu4(float4 a) {
    a.x = fast_silu(a.x);
    a.y = fast_silu(a.y);
    a.z = fast_silu(a.z);
    a.w = fast_silu(a.w);
    return a;
}
__device__ __forceinline__ float4 fma4(float4 a, float4 b, float4 c) {
    return make_float4(fmaf(a.x, b.x, c.x), fmaf(a.y, b.y, c.y),
                       fmaf(a.z, b.z, c.z), fmaf(a.w, b.w, c.w));
}

// ---------------------------------------------------------------------------
// Depthwise causal conv1d + bias + SiLU. half in, half out. 16 l per thread.
// ---------------------------------------------------------------------------
__global__ __launch_bounds__(256)
void conv_silu_kernel(const __half* __restrict__ xzh,
                      const float* __restrict__ cw,
                      const float* __restrict__ cb,
                      __half* __restrict__ uh) {
    int idx = blockIdx.x * blockDim.x + threadIdx.x;   // (ROWS/16)*(DI/4)
    int dq = idx & (DI / 4 - 1);
    int g = idx >> 9;
    int l0 = (g & (LL / 16 - 1)) * 16;
    int b = g >> 8;
    size_t bl0 = (size_t)b * LL + l0;
    const int d = dq * 4;

    float4 r0 = *(const float4*)(cw + (d + 0) * KC);
    float4 r1 = *(const float4*)(cw + (d + 1) * KC);
    float4 r2 = *(const float4*)(cw + (d + 2) * KC);
    float4 r3 = *(const float4*)(cw + (d + 3) * KC);
    float4 w0 = make_float4(r0.x, r1.x, r2.x, r3.x);
    float4 w1 = make_float4(r0.y, r1.y, r2.y, r3.y);
    float4 w2 = make_float4(r0.z, r1.z, r2.z, r3.z);
    float4 w3 = make_float4(r0.w, r1.w, r2.w, r3.w);
    float4 bias = *(const float4*)(cb + d);

    float4 xm3 = make_float4(0, 0, 0, 0), xm2 = xm3, xm1 = xm3;
    if (l0 > 0) {
        xm3 = load_half4(xzh + (bl0 - 3) * (2 * DI) + d);
        xm2 = load_half4(xzh + (bl0 - 2) * (2 * DI) + d);
        xm1 = load_half4(xzh + (bl0 - 1) * (2 * DI) + d);
    }
    #pragma unroll
    for (int j = 0; j < 16; j++) {
        float4 xc = load_half4(xzh + (bl0 + j) * (2 * DI) + d);
        float4 acc = bias;
        acc = fma4(w0, xm3, acc);
        acc = fma4(w1, xm2, acc);
        acc = fma4(w2, xm1, acc);
        acc = fma4(w3, xc, acc);
        store_half4(uh + (bl0 + j) * DI + d, silu4(acc));
        xm3 = xm2; xm2 = xm1; xm1 = xc;
    }
}

// ---------------------------------------------------------------------------
// Warp-parallel carry scan: one warp per (b, d) channel, 2 chunks per lane.
// ---------------------------------------------------------------------------
__global__ __launch_bounds__(256)
void carry_kernel(const float* __restrict__ S, const float* __restrict__ P,
                  float* __restrict__ Cy) {
    const int gw = (blockIdx.x * blockDim.x + threadIdx.x) >> 5;  // < BB*DI
    const int lane = threadIdx.x & 31;
    const int b = gw / DI;
    const int d = gw - b * DI;

    const int c0 = 2 * lane;
    const size_t i0 = ((size_t)b * NCH + c0) * DI + d;
    const size_t i1 = i0 + DI;

    float p0 = P[i0], s0 = S[i0];
    float p1 = P[i1], s1 = S[i1];

    float lp = p0 * p1;
    float ls = fmaf(s0, p1, s1);

    #pragma unroll
    for (int off = 1; off < 32; off <<= 1) {
        float pp = __shfl_up_sync(0xFFFFFFFFu, lp, off);
        float ss = __shfl_up_sync(0xFFFFFFFFu, ls, off);
        if (lane >= off) {
            ls = fmaf(ss, lp, ls);
            lp = pp * lp;
        }
    }

    float prev_s = __shfl_up_sync(0xFFFFFFFFu, ls, 1);
    if (lane == 0) prev_s = 0.f;
    Cy[i0] = clip1e4(prev_s);
    Cy[i1] = clip1e4(fmaf(prev_s, p0, s0));
}

// ---------------------------------------------------------------------------
// Scan pass2 (e f16, fast silu gate)
// ---------------------------------------------------------------------------
__global__ __launch_bounds__(256)
void scan_pass2(const __half* __restrict__ eh, const __half* __restrict__ uh,
                const __half* __restrict__ xzh, const float* __restrict__ Dvec,
                const float* __restrict__ Cy, __half* __restrict__ ygh) {
    int gid = blockIdx.x * blockDim.x + threadIdx.x;
    int dq = gid & (DI / 4 - 1);
    int bc = gid / (DI / 4);
    int c = bc & (NCH - 1);
    int b = bc / NCH;
    size_t base  = ((size_t)b * LL + (size_t)c * LC) * DI + dq * 4;
    size_t zbase = ((size_t)b * LL + (size_t)c * LC) * (2 * DI) + DI + dq * 4;
    float4 Dd = *(const float4*)(Dvec + dq * 4);
    float4 st = ((const float4*)Cy)[gid];
    #pragma unroll 4
    for (int l = 0; l < LC; l++) {
        float4 et = load_half4(eh + base + (size_t)l * DI);
        float4 ut = load_half4(uh + base + (size_t)l * DI);
        float4 zt = load_half4(xzh + zbase + (size_t)l * (2 * DI));
        st.x = clip1e4(fmaf(st.x, et.x, ut.x));
        st.y = clip1e4(fmaf(st.y, et.y, ut.y));
        st.z = clip1e4(fmaf(st.z, et.z, ut.z));
        st.w = clip1e4(fmaf(st.w, et.w, ut.w));
        float4 o;
        o.x = clip1e4(fmaf(ut.x, Dd.x, st.x)) * fast_silu(zt.x);
        o.y = clip1e4(fmaf(ut.y, Dd.y, st.y)) * fast_silu(zt.y);
        o.z = clip1e4(fmaf(ut.z, Dd.z, st.z)) * fast_silu(zt.z);
        o.w = clip1e4(fmaf(ut.w, Dd.w, st.w)) * fast_silu(zt.w);
        store_half4(ygh + base + (size_t)l * DI, o);
    }
}

// ---------------------------------------------------------------------------
// Launch
// ---------------------------------------------------------------------------
extern "C" void kernel_launch(void* const* d_in, const int* in_sizes, int n_in,
                              void* d_out, int out_size) {
    const float* x     = (const float*)d_in[0];
    const float* inw   = (const float*)d_in[1];
    const float* convw = (const float*)d_in[2];
    const float* convb = (const float*)d_in[3];
    const float* xpw   = (const float*)d_in[4];
    const float* dtw   = (const float*)d_in[5];
    const float* dtb   = (const float*)d_in[6];
    const float* alog  = (const float*)d_in[7];
    const float* Dvec  = (const float*)d_in[8];
    const float* outw  = (const float*)d_in[9];
    float* out = (float*)d_out;

    float *S, *P, *Cy, *dtp, *Aclip;
    __half *xzh, *uh, *dtlowh, *eh, *ygh, *xh, *inwh, *outwh, *xpwh, *dtwh;
    cudaGetSymbolAddress((void**)&xzh, g_xzh);
    cudaGetSymbolAddress((void**)&uh, g_uh);
    cudaGetSymbolAddress((void**)&dtp, g_dtp);
    cudaGetSymbolAddress((void**)&dtlowh, g_dtlowh);
    cudaGetSymbolAddress((void**)&eh, g_eh);
    cudaGetSymbolAddress((void**)&ygh, g_ygh);
    cudaGetSymbolAddress((void**)&S, g_S);
    cudaGetSymbolAddress((void**)&P, g_P);
    cudaGetSymbolAddress((void**)&Cy, g_C);
    cudaGetSymbolAddress((void**)&Aclip, g_Aclip);
    cudaGetSymbolAddress((void**)&xh, g_xh);
    cudaGetSymbolAddress((void**)&inwh, g_inwh);
    cudaGetSymbolAddress((void**)&outwh, g_outwh);
    cudaGetSymbolAddress((void**)&xpwh, g_xpwh);
    cudaGetSymbolAddress((void**)&dtwh, g_dtwh);

    const int SM128 = 2 * (128 * SSTH + 128 * SSTH) * 2;   // 73728 B
    const int SM64  = 2 * (128 * SSTH + 64 * SSTH) * 2;    // 55296 B
    cudaFuncSetAttribute((const void*)gemm_f16<128, 0, false>,
                         cudaFuncAttributeMaxDynamicSharedMemorySize, SM128);
    cudaFuncSetAttribute((const void*)gemm_f16<128, 2, false>,
                         cudaFuncAttributeMaxDynamicSharedMemorySize, SM128);
    cudaFuncSetAttribute((const void*)gemm_f16<128, 3, false>,
                         cudaFuncAttributeMaxDynamicSharedMemorySize, SM128);
    cudaFuncSetAttribute((const void*)gemm_f16<64, 0, true>,
                         cudaFuncAttributeMaxDynamicSharedMemorySize, SM64);

    // 0. batched prepass (conversions + Aclip)
    prep_all_kernel<<<(N8_TOT + 255) / 256, 256>>>(
        x, xh, inw, inwh, outw, outwh, xpw, xpwh, dtw, dtwh, alog, Aclip);

    // 1. in_proj: xzh[8192,4096] = xh * inwh^T (K=1024), half output
    gemm_f16<128, 3, false><<<dim3((2 * DI) / 128, ROWS / 128), 256, SM128>>>(
        xh, inwh, nullptr, xzh, ROWS, 2 * DI, DMOD, DMOD,
        nullptr, nullptr, nullptr, nullptr, nullptr);
    // 2. conv + silu -> uh
    conv_silu_kernel<<<(ROWS / 16) * (DI / 4) / 256, 256>>>(xzh, convw, convb, uh);
    // 3. dtlow split-K (x4) + reduce
    gemm_f16<64, 0, true><<<dim3(1, ROWS / 128, NSPLIT), 256, SM64>>>(
        uh, xpwh, dtp, nullptr, ROWS, DTR, DI, KSL,
        nullptr, nullptr, nullptr, nullptr, nullptr);
    dtred_kernel<<<(ROWS * DTR / 4) / 256, 256>>>(dtp, dtlowh);
    // 4. e = f(dtlowh * dtwh^T + dtb) (K=64, half out) + fused pass1 -> S, P
    gemm_f16<128, 2, false><<<dim3(DI / 128, ROWS / 128), 256, SM128>>>(
        dtlowh, dtwh, nullptr, eh, ROWS, DI, DTR, DTR,
        dtb, Aclip, uh, S, P);
    // 5. warp-parallel carry + scan pass2
    carry_kernel<<<(BB * DI * 32) / 256, 256>>>(S, P, Cy);
    scan_pass2<<<(BB * NCH * DI / 4) / 256, 256>>>(eh, uh, xzh, Dvec, Cy, ygh);
    // 6. out_proj: out[8192,1024] = ygh * outwh^T (K=2048), f32 output
    gemm_f16<128, 0, false><<<dim3(DMOD / 128, ROWS / 128), 256, SM128>>>(
        ygh, outwh, out, nullptr, ROWS, DMOD, DI, DI,
        nullptr, nullptr, nullptr, nullptr, nullptr);
}

// round 16
// speedup vs baseline: 1.0192x; 1.0160x over previous
#include <cuda_runtime.h>
#include <cuda_fp16.h>
#include <math.h>
#include <stdint.h>

// ---------------------------------------------------------------------------
// Problem constants
// ---------------------------------------------------------------------------
#define BB 2
#define LL 4096
#define DMOD 1024
#define DI 2048
#define DTR 64
#define KC 4
#define ROWS (BB * LL)       // 8192
#define NCH 64               // scan chunks
#define LC (LL / NCH)        // 64
#define NSPLIT 4             // dtlow split-K factor
#define KSL (DI / NSPLIT)    // 512

// ---------------------------------------------------------------------------
// Scratch (device globals; no allocation allowed)
// ---------------------------------------------------------------------------
__device__ __half g_xzh[(size_t)ROWS * 2 * DI];    // in_proj out (xi | z), f16
__device__ __half g_uh[(size_t)ROWS * DI];         // conv+silu out f16
__device__ float  g_dtp[(size_t)NSPLIT * ROWS * DTR];
__device__ __half g_dtlowh[(size_t)ROWS * DTR];
__device__ __half g_eh[(size_t)ROWS * DI];         // decay factors f16
__device__ __half g_ygh[(size_t)ROWS * DI];        // gated scan out f16
__device__ float  g_S [(size_t)BB * NCH * DI];
__device__ float  g_P [(size_t)BB * NCH * DI];
__device__ float  g_C [(size_t)BB * NCH * DI];
__device__ float  g_Aclip[DI];                     // clip(-exp(A_log))
// fp16 operand copies
__device__ __half g_xh  [(size_t)ROWS * DMOD];
__device__ __half g_inwh[(size_t)2 * DI * DMOD];
__device__ __half g_outwh[(size_t)DMOD * DI];
__device__ __half g_xpwh[(size_t)DTR * DI];
__device__ __half g_dtwh[(size_t)DI * DTR];

// ---------------------------------------------------------------------------
// PTX helpers (generic ISA: cp.async + ldmatrix + mma.sync f16 — sm_103-safe)
// ---------------------------------------------------------------------------
__device__ __forceinline__ uint32_t smem_u32(const void* p) {
    uint32_t a;
    asm("{ .reg .u64 t; cvta.to.shared.u64 t, %1; cvt.u32.u64 %0, t; }"
        : "=r"(a) : "l"(p));
    return a;
}
__device__ __forceinline__ void cp_async16(uint32_t dst, const void* src) {
    asm volatile("cp.async.cg.shared.global [%0], [%1], 16;"
                 :: "r"(dst), "l"(src) : "memory");
}
#define CP_COMMIT() asm volatile("cp.async.commit_group;" ::: "memory")
#define CP_WAIT(n)  asm volatile("cp.async.wait_group %0;" :: "n"(n) : "memory")

__device__ __forceinline__ void ldsm_x4(uint32_t* d, uint32_t addr) {
    asm volatile("ldmatrix.sync.aligned.m8n8.x4.shared.b16 {%0,%1,%2,%3}, [%4];"
                 : "=r"(d[0]), "=r"(d[1]), "=r"(d[2]), "=r"(d[3]) : "r"(addr));
}
__device__ __forceinline__ void mma_f16(float* c, const uint32_t* a, const uint32_t* b) {
    asm volatile(
        "mma.sync.aligned.m16n8k16.row.col.f32.f16.f16.f32 "
        "{%0,%1,%2,%3}, {%4,%5,%6,%7}, {%8,%9}, {%0,%1,%2,%3};"
        : "+f"(c[0]), "+f"(c[1]), "+f"(c[2]), "+f"(c[3])
        : "r"(a[0]), "r"(a[1]), "r"(a[2]), "r"(a[3]), "r"(b[0]), "r"(b[1]));
}

// Fast e-path: A pre-clipped; __expf/__logf intrinsics.
__device__ __forceinline__ float e_from_dpre(float acc, float bias, float A) {
    float v = acc + bias;
    float delta = (v > 20.f) ? v : __logf(1.f + __expf(v));
    delta = fminf(fmaxf(delta, 1e-6f), 10.f);
    float ev = __expf(delta * A);
    return fminf(fmaxf(ev, 1e-6f), 1.f);
}
__device__ __forceinline__ float clip1e4(float v) {
    return fminf(fmaxf(v, -1e4f), 1e4f);
}
__device__ __forceinline__ float fast_silu(float a) {
    return __fdividef(a, 1.f + __expf(-a));
}

// ---------------------------------------------------------------------------
// fp16 tensor-core GEMM (best config): C[M,N] = A[M,K]*B[N,K]^T.
// BM=128, BN template. BK=64 halves. 256 threads, 8 warps (2x4),
// 2-stage cp.async double buffer. SSTH=72 halves -> conflict-free ldmatrix.
// EPI: 0 = f32 store; 2 = fused e-epilogue + scan pass1 (e AND u tiles in
//      smem as f16, stride 136 halves; u loaded cooperatively/coalesced);
//      3 = half store to Ch.
// ---------------------------------------------------------------------------
#define SSTH 72
#define BKH  64
#define EST2 136   // e/u smem tile stride in halves (16B-aligned rows)

template <int BN, int EPI, bool SPLITK>
__global__ __launch_bounds__(256, 2)
void gemm_f16(const __half* __restrict__ A, const __half* __restrict__ B,
              float* __restrict__ C, __half* __restrict__ Ch,
              int M, int N, int Kst, int Ksl,
              const float* __restrict__ vb1, const float* __restrict__ vb2,
              const __half* __restrict__ U,
              float* __restrict__ Sp, float* __restrict__ Pp) {
    constexpr int MT = 4;
    constexpr int NT = BN / 32;
    constexpr int NPAIR = NT / 2;
    constexpr int AF = (128 * 8) / 256;
    constexpr int BF = (BN * 8) / 256;

    extern __shared__ __half smem[];
    const uint32_t sA = smem_u32(smem);
    const uint32_t sB = sA + 2 * 128 * SSTH * 2;

    const int tid = threadIdx.x;
    const int wid = tid >> 5;
    const int lane = tid & 31;
    const int grp = lane >> 2;
    const int qid = lane & 3;
    const int wm = wid >> 2;
    const int wn = wid & 3;

    const int bx = blockIdx.x, by = blockIdx.y;
    const int K = Kst;
    const __half* Ag = A + (size_t)by * 128 * K;
    const __half* Bg = B + (size_t)bx * BN * K;
    if (SPLITK) {
        Ag += (size_t)blockIdx.z * Ksl;
        Bg += (size_t)blockIdx.z * Ksl;
        C  += (size_t)blockIdx.z * M * N;
    }

    const int a_row = lane & 15;
    const int a_kb  = (lane >> 4) * 16;
    const int b_row = ((lane >> 4) << 3) + (lane & 7);
    const int b_kb  = ((lane >> 3) & 1) * 16;

    float acc[MT][NT][4];
    #pragma unroll
    for (int i = 0; i < MT; i++)
        #pragma unroll
        for (int j = 0; j < NT; j++)
            #pragma unroll
            for (int q = 0; q < 4; q++) acc[i][j][q] = 0.f;

    const int nK = Ksl / BKH;

    // prologue: tile 0 -> buf 0
    #pragma unroll
    for (int t = 0; t < AF; t++) {
        int f = tid + t * 256;
        int row = f >> 3, c = f & 7;
        cp_async16(sA + row * 144 + c * 16, Ag + (size_t)row * K + c * 8);
    }
    #pragma unroll
    for (int t = 0; t < BF; t++) {
        int f = tid + t * 256;
        int row = f >> 3, c = f & 7;
        cp_async16(sB + row * 144 + c * 16, Bg + (size_t)row * K + c * 8);
    }
    CP_COMMIT();

    int buf = 0;
    for (int kt = 0; kt < nK; kt++) {
        if (kt + 1 < nK) {
            const uint32_t dA = sA + (buf ^ 1) * 128 * SSTH * 2;
            const uint32_t dB = sB + (buf ^ 1) * BN * SSTH * 2;
            const int koff = (kt + 1) * BKH;
            #pragma unroll
            for (int t = 0; t < AF; t++) {
                int f = tid + t * 256;
                int row = f >> 3, c = f & 7;
                cp_async16(dA + row * 144 + c * 16, Ag + (size_t)row * K + koff + c * 8);
            }
            #pragma unroll
            for (int t = 0; t < BF; t++) {
                int f = tid + t * 256;
                int row = f >> 3, c = f & 7;
                cp_async16(dB + row * 144 + c * 16, Bg + (size_t)row * K + koff + c * 8);
            }
            CP_COMMIT();
            CP_WAIT(1);
        } else {
            CP_WAIT(0);
        }
        __syncthreads();

        const uint32_t Ab = sA + buf * 128 * SSTH * 2;
        const uint32_t Bb = sB + buf * BN * SSTH * 2;

        uint32_t addrA[MT], addrB[NPAIR];
        #pragma unroll
        for (int mt = 0; mt < MT; mt++)
            addrA[mt] = Ab + (wm * 64 + mt * 16 + a_row) * 144 + a_kb;
        #pragma unroll
        for (int p = 0; p < NPAIR; p++)
            addrB[p] = Bb + (wn * (NT * 8) + p * 16 + b_row) * 144 + b_kb;

        #pragma unroll
        for (int s = 0; s < BKH / 16; s++) {
            uint32_t af[MT][4];
            #pragma unroll
            for (int mt = 0; mt < MT; mt++)
                ldsm_x4(af[mt], addrA[mt] + s * 32);
            uint32_t bf[NPAIR][4];
            #pragma unroll
            for (int p = 0; p < NPAIR; p++)
                ldsm_x4(bf[p], addrB[p] + s * 32);
            #pragma unroll
            for (int mt = 0; mt < MT; mt++)
                #pragma unroll
                for (int nt = 0; nt < NT; nt++)
                    mma_f16(acc[mt][nt], af[mt], &bf[nt >> 1][(nt & 1) * 2]);
        }
        __syncthreads();
        buf ^= 1;
    }

    __half* seh = smem;                 // e-tile stash (EPI==2), 128 x EST2 halves
    __half* su  = smem + 128 * EST2;    // u-tile (EPI==2), 128 x EST2 halves

    // epilogue
    #pragma unroll
    for (int mt = 0; mt < MT; mt++) {
        const int rl = wm * 64 + mt * 16 + grp;
        const int r0 = by * 128 + rl;
        #pragma unroll
        for (int nt = 0; nt < NT; nt++) {
            const int cl = wn * (NT * 8) + nt * 8 + qid * 2;
            const int c0 = bx * BN + cl;
            float o0 = acc[mt][nt][0], o1 = acc[mt][nt][1];
            float o2 = acc[mt][nt][2], o3 = acc[mt][nt][3];
            if (EPI == 2) {
                float2 bb = *(const float2*)(vb1 + c0);
                float2 aa = *(const float2*)(vb2 + c0);   // pre-clipped A
                o0 = e_from_dpre(o0, bb.x, aa.x); o1 = e_from_dpre(o1, bb.y, aa.y);
                o2 = e_from_dpre(o2, bb.x, aa.x); o3 = e_from_dpre(o3, bb.y, aa.y);
                __half2 e01 = __floats2half2_rn(o0, o1);
                __half2 e23 = __floats2half2_rn(o2, o3);
                *(__half2*)(seh + rl * EST2 + cl) = e01;
                *(__half2*)(seh + (rl + 8) * EST2 + cl) = e23;
                *(__half2*)(Ch + (size_t)r0 * N + c0) = e01;
                *(__half2*)(Ch + (size_t)(r0 + 8) * N + c0) = e23;
            } else if (EPI == 3) {
                *(__half2*)(Ch + (size_t)r0 * N + c0) = __floats2half2_rn(o0, o1);
                *(__half2*)(Ch + (size_t)(r0 + 8) * N + c0) = __floats2half2_rn(o2, o3);
            } else {
                *(float2*)(C + (size_t)r0 * N + c0) = make_float2(o0, o1);
                *(float2*)(C + (size_t)(r0 + 8) * N + c0) = make_float2(o2, o3);
            }
        }
    }

    if (EPI == 2) {
        // Cooperative coalesced u-tile load: 128 rows x 128 halves.
        // 2048 uint4 chunks, 8 per thread.
        const __half* Ug = U + (size_t)by * 128 * N + bx * BN;
        #pragma unroll
        for (int t = 0; t < 8; t++) {
            int f = tid + t * 256;
            int row = f >> 4, c = f & 15;   // 16 chunks of 8 halves per row
            uint4 v = *(const uint4*)(Ug + (size_t)row * N + c * 8);
            *(uint4*)(su + row * EST2 + c * 8) = v;
        }
        __syncthreads();

        // fused scan pass1: 2 chunks x 128 d per block, one thread each.
        // Both e and u read from smem (f16; bit-identical to pass2's inputs).
        const int ci = tid >> 7;
        const int dl = tid & 127;
        const size_t row0 = (size_t)by * 128 + ci * 64;
        const int b = (int)(row0 >> 12);
        const int c = (int)((row0 & 4095) >> 6);
        const int d = bx * BN + dl;
        const __half* ep = seh + ci * 64 * EST2 + dl;
        const __half* up = su + ci * 64 * EST2 + dl;
        float st = 0.f, pr = 1.f;
        #pragma unroll 8
        for (int l = 0; l < LC; l++) {
            float et = __half2float(ep[l * EST2]);
            float ut = __half2float(up[l * EST2]);
            st = clip1e4(fmaf(st, et, ut));
            pr *= et;
        }
        const size_t gi = ((size_t)b * NCH + c) * DI + d;
        Sp[gi] = st;
        Pp[gi] = pr;
    }
}

// ---------------------------------------------------------------------------
// Batched prepass: f32 -> f16 conversions + Aclip precompute.
// ---------------------------------------------------------------------------
#define N8_X    (ROWS * DMOD / 8)
#define N8_INW  (2 * DI * DMOD / 8)
#define N8_OUTW (DMOD * DI / 8)
#define N8_XPW  (DTR * DI / 8)
#define N8_DTW  (DI * DTR / 8)
#define N8_ACL  (DI / 8)
#define N8_TOT  (N8_X + N8_INW + N8_OUTW + N8_XPW + N8_DTW + N8_ACL)

__device__ __forceinline__ void cvt8(const float* in, __half* out, int i) {
    float4 v0 = ((const float4*)in)[2 * i];
    float4 v1 = ((const float4*)in)[2 * i + 1];
    __half2 h0 = __floats2half2_rn(v0.x, v0.y);
    __half2 h1 = __floats2half2_rn(v0.z, v0.w);
    __half2 h2 = __floats2half2_rn(v1.x, v1.y);
    __half2 h3 = __floats2half2_rn(v1.z, v1.w);
    uint4 o;
    o.x = *(uint32_t*)&h0; o.y = *(uint32_t*)&h1;
    o.z = *(uint32_t*)&h2; o.w = *(uint32_t*)&h3;
    ((uint4*)out)[i] = o;
}

__global__ __launch_bounds__(256)
void prep_all_kernel(const float* x, __half* xh,
                     const float* inw, __half* inwh,
                     const float* outw, __half* outwh,
                     const float* xpw, __half* xpwh,
                     const float* dtw, __half* dtwh,
                     const float* alog, float* Aclip) {
    int i = blockIdx.x * blockDim.x + threadIdx.x;
    if (i < N8_X) { cvt8(x, xh, i); return; }
    i -= N8_X;
    if (i < N8_INW) { cvt8(inw, inwh, i); return; }
    i -= N8_INW;
    if (i < N8_OUTW) { cvt8(outw, outwh, i); return; }
    i -= N8_OUTW;
    if (i < N8_XPW) { cvt8(xpw, xpwh, i); return; }
    i -= N8_XPW;
    if (i < N8_DTW) { cvt8(dtw, dtwh, i); return; }
    i -= N8_DTW;
    if (i < N8_ACL) {
        #pragma unroll
        for (int j = 0; j < 8; j++) {
            int d = i * 8 + j;
            Aclip[d] = fminf(fmaxf(-expf(alog[d]), -10.f), -1e-6f);
        }
    }
}

// ---------------------------------------------------------------------------
// dtlow split-K reduce: sum NSPLIT f32 partials -> half.
// ---------------------------------------------------------------------------
__global__ __launch_bounds__(256)
void dtred_kernel(const float* __restrict__ dtp, __half* __restrict__ dtlowh) {
    int i = blockIdx.x * blockDim.x + threadIdx.x;     // < ROWS*DTR/4
    const int STRIDE4 = ROWS * DTR / 4;
    float4 s = ((const float4*)dtp)[i];
    #pragma unroll
    for (int p = 1; p < NSPLIT; p++) {
        float4 v = ((const float4*)dtp)[i + p * STRIDE4];
        s.x += v.x; s.y += v.y; s.z += v.z; s.w += v.w;
    }
    __half2 lo = __floats2half2_rn(s.x, s.y);
    __half2 hi = __floats2half2_rn(s.z, s.w);
    uint2 o; o.x = *(uint32_t*)&lo; o.y = *(uint32_t*)&hi;
    ((uint2*)dtlowh)[i] = o;
}

// ---------------------------------------------------------------------------
// half4 helpers
// ---------------------------------------------------------------------------
__device__ __forceinline__ void store_half4(__half* p, float4 v) {
    __half2 lo = __floats2half2_rn(v.x, v.y);
    __half2 hi = __floats2half2_rn(v.z, v.w);
    uint2 o; o.x = *(uint32_t*)&lo; o.y = *(uint32_t*)&hi;
    *(uint2*)p = o;
}
__device__ __forceinline__ float4 load_half4(const __half* p) {
    uint2 v = *(const uint2*)p;
    float2 f0 = __half22float2(*(__half2*)&v.x);
    float2 f1 = __half22float2(*(__half2*)&v.y);
    return make_float4(f0.x, f0.y, f1.x, f1.y);
}
__device__ __forceinline__ float4 silu4(float4 a) {
    a.x = fast_silu(a.x);
    a.y = fast_silu(a.y);
    a.z = fast_silu(a.z);
    a.w = fast_silu(a.w);
    return a;
}
__device__ __forceinline__ float4 fma4(float4 a, float4 b, float4 c) {
    return make_float4(fmaf(a.x, b.x, c.x), fmaf(a.y, b.y, c.y),
                       fmaf(a.z, b.z, c.z), fmaf(a.w, b.w, c.w));
}

// ---------------------------------------------------------------------------
// Depthwise causal conv1d + bias + SiLU. half in, half out. 16 l per thread.
// ---------------------------------------------------------------------------
__global__ __launch_bounds__(256)
void conv_silu_kernel(const __half* __restrict__ xzh,
                      const float* __restrict__ cw,
                      const float* __restrict__ cb,
                      __half* __restrict__ uh) {
    int idx = blockIdx.x * blockDim.x + threadIdx.x;   // (ROWS/16)*(DI/4)
    int dq = idx & (DI / 4 - 1);
    int g = idx >> 9;
    int l0 = (g & (LL / 16 - 1)) * 16;
    int b = g >> 8;
    size_t bl0 = (size_t)b * LL + l0;
    const int d = dq * 4;

    float4 r0 = *(const float4*)(cw + (d + 0) * KC);
    float4 r1 = *(const float4*)(cw + (d + 1) * KC);
    float4 r2 = *(const float4*)(cw + (d + 2) * KC);
    float4 r3 = *(const float4*)(cw + (d + 3) * KC);
    float4 w0 = make_float4(r0.x, r1.x, r2.x, r3.x);
    float4 w1 = make_float4(r0.y, r1.y, r2.y, r3.y);
    float4 w2 = make_float4(r0.z, r1.z, r2.z, r3.z);
    float4 w3 = make_float4(r0.w, r1.w, r2.w, r3.w);
    float4 bias = *(const float4*)(cb + d);

    float4 xm3 = make_float4(0, 0, 0, 0), xm2 = xm3, xm1 = xm3;
    if (l0 > 0) {
        xm3 = load_half4(xzh + (bl0 - 3) * (2 * DI) + d);
        xm2 = load_half4(xzh + (bl0 - 2) * (2 * DI) + d);
        xm1 = load_half4(xzh + (bl0 - 1) * (2 * DI) + d);
    }
    #pragma unroll
    for (int j = 0; j < 16; j++) {
        float4 xc = load_half4(xzh + (bl0 + j) * (2 * DI) + d);
        float4 acc = bias;
        acc = fma4(w0, xm3, acc);
        acc = fma4(w1, xm2, acc);
        acc = fma4(w2, xm1, acc);
        acc = fma4(w3, xc, acc);
        store_half4(uh + (bl0 + j) * DI + d, silu4(acc));
        xm3 = xm2; xm2 = xm1; xm1 = xc;
    }
}

// ---------------------------------------------------------------------------
// Warp-parallel carry scan: one warp per (b, d) channel, 2 chunks per lane.
// ---------------------------------------------------------------------------
__global__ __launch_bounds__(256)
void carry_kernel(const float* __restrict__ S, const float* __restrict__ P,
                  float* __restrict__ Cy) {
    const int gw = (blockIdx.x * blockDim.x + threadIdx.x) >> 5;  // < BB*DI
    const int lane = threadIdx.x & 31;
    const int b = gw / DI;
    const int d = gw - b * DI;

    const int c0 = 2 * lane;
    const size_t i0 = ((size_t)b * NCH + c0) * DI + d;
    const size_t i1 = i0 + DI;

    float p0 = P[i0], s0 = S[i0];
    float p1 = P[i1], s1 = S[i1];

    float lp = p0 * p1;
    float ls = fmaf(s0, p1, s1);

    #pragma unroll
    for (int off = 1; off < 32; off <<= 1) {
        float pp = __shfl_up_sync(0xFFFFFFFFu, lp, off);
        float ss = __shfl_up_sync(0xFFFFFFFFu, ls, off);
        if (lane >= off) {
            ls = fmaf(ss, lp, ls);
            lp = pp * lp;
        }
    }

    float prev_s = __shfl_up_sync(0xFFFFFFFFu, ls, 1);
    if (lane == 0) prev_s = 0.f;
    Cy[i0] = clip1e4(prev_s);
    Cy[i1] = clip1e4(fmaf(prev_s, p0, s0));
}

// ---------------------------------------------------------------------------
// Scan pass2 (e f16, fast silu gate)
// ---------------------------------------------------------------------------
__global__ __launch_bounds__(256)
void scan_pass2(const __half* __restrict__ eh, const __half* __restrict__ uh,
                const __half* __restrict__ xzh, const float* __restrict__ Dvec,
                const float* __restrict__ Cy, __half* __restrict__ ygh) {
    int gid = blockIdx.x * blockDim.x + threadIdx.x;
    int dq = gid & (DI / 4 - 1);
    int bc = gid / (DI / 4);
    int c = bc & (NCH - 1);
    int b = bc / NCH;
    size_t base  = ((size_t)b * LL + (size_t)c * LC) * DI + dq * 4;
    size_t zbase = ((size_t)b * LL + (size_t)c * LC) * (2 * DI) + DI + dq * 4;
    float4 Dd = *(const float4*)(Dvec + dq * 4);
    float4 st = ((const float4*)Cy)[gid];
    #pragma unroll 4
    for (int l = 0; l < LC; l++) {
        float4 et = load_half4(eh + base + (size_t)l * DI);
        float4 ut = load_half4(uh + base + (size_t)l * DI);
        float4 zt = load_half4(xzh + zbase + (size_t)l * (2 * DI));
        st.x = clip1e4(fmaf(st.x, et.x, ut.x));
        st.y = clip1e4(fmaf(st.y, et.y, ut.y));
        st.z = clip1e4(fmaf(st.z, et.z, ut.z));
        st.w = clip1e4(fmaf(st.w, et.w, ut.w));
        float4 o;
        o.x = clip1e4(fmaf(ut.x, Dd.x, st.x)) * fast_silu(zt.x);
        o.y = clip1e4(fmaf(ut.y, Dd.y, st.y)) * fast_silu(zt.y);
        o.z = clip1e4(fmaf(ut.z, Dd.z, st.z)) * fast_silu(zt.z);
        o.w = clip1e4(fmaf(ut.w, Dd.w, st.w)) * fast_silu(zt.w);
        store_half4(ygh + base + (size_t)l * DI, o);
    }
}

// ---------------------------------------------------------------------------
// Launch
// ---------------------------------------------------------------------------
extern "C" void kernel_launch(void* const* d_in, const int* in_sizes, int n_in,
                              void* d_out, int out_size) {
    const float* x     = (const float*)d_in[0];
    const float* inw   = (const float*)d_in[1];
    const float* convw = (const float*)d_in[2];
    const float* convb = (const float*)d_in[3];
    const float* xpw   = (const float*)d_in[4];
    const float* dtw   = (const float*)d_in[5];
    const float* dtb   = (const float*)d_in[6];
    const float* alog  = (const float*)d_in[7];
    const float* Dvec  = (const float*)d_in[8];
    const float* outw  = (const float*)d_in[9];
    float* out = (float*)d_out;

    float *S, *P, *Cy, *dtp, *Aclip;
    __half *xzh, *uh, *dtlowh, *eh, *ygh, *xh, *inwh, *outwh, *xpwh, *dtwh;
    cudaGetSymbolAddress((void**)&xzh, g_xzh);
    cudaGetSymbolAddress((void**)&uh, g_uh);
    cudaGetSymbolAddress((void**)&dtp, g_dtp);
    cudaGetSymbolAddress((void**)&dtlowh, g_dtlowh);
    cudaGetSymbolAddress((void**)&eh, g_eh);
    cudaGetSymbolAddress((void**)&ygh, g_ygh);
    cudaGetSymbolAddress((void**)&S, g_S);
    cudaGetSymbolAddress((void**)&P, g_P);
    cudaGetSymbolAddress((void**)&Cy, g_C);
    cudaGetSymbolAddress((void**)&Aclip, g_Aclip);
    cudaGetSymbolAddress((void**)&xh, g_xh);
    cudaGetSymbolAddress((void**)&inwh, g_inwh);
    cudaGetSymbolAddress((void**)&outwh, g_outwh);
    cudaGetSymbolAddress((void**)&xpwh, g_xpwh);
    cudaGetSymbolAddress((void**)&dtwh, g_dtwh);

    const int SM128 = 2 * (128 * SSTH + 128 * SSTH) * 2;   // 73728 B (>= 2*128*EST2*2)
    const int SM64  = 2 * (128 * SSTH + 64 * SSTH) * 2;    // 55296 B
    cudaFuncSetAttribute((const void*)gemm_f16<128, 0, false>,
                         cudaFuncAttributeMaxDynamicSharedMemorySize, SM128);
    cudaFuncSetAttribute((const void*)gemm_f16<128, 2, false>,
                         cudaFuncAttributeMaxDynamicSharedMemorySize, SM128);
    cudaFuncSetAttribute((const void*)gemm_f16<128, 3, false>,
                         cudaFuncAttributeMaxDynamicSharedMemorySize, SM128);
    cudaFuncSetAttribute((const void*)gemm_f16<64, 0, true>,
                         cudaFuncAttributeMaxDynamicSharedMemorySize, SM64);

    // 0. batched prepass (conversions + Aclip)
    prep_all_kernel<<<(N8_TOT + 255) / 256, 256>>>(
        x, xh, inw, inwh, outw, outwh, xpw, xpwh, dtw, dtwh, alog, Aclip);

    // 1. in_proj: xzh[8192,4096] = xh * inwh^T (K=1024), half output
    gemm_f16<128, 3, false><<<dim3((2 * DI) / 128, ROWS / 128), 256, SM128>>>(
        xh, inwh, nullptr, xzh, ROWS, 2 * DI, DMOD, DMOD,
        nullptr, nullptr, nullptr, nullptr, nullptr);
    // 2. conv + silu -> uh
    conv_silu_kernel<<<(ROWS / 16) * (DI / 4) / 256, 256>>>(xzh, convw, convb, uh);
    // 3. dtlow split-K (x4) + reduce
    gemm_f16<64, 0, true><<<dim3(1, ROWS / 128, NSPLIT), 256, SM64>>>(
        uh, xpwh, dtp, nullptr, ROWS, DTR, DI, KSL,
        nullptr, nullptr, nullptr, nullptr, nullptr);
    dtred_kernel<<<(ROWS * DTR / 4) / 256, 256>>>(dtp, dtlowh);
    // 4. e = f(dtlowh * dtwh^T + dtb) (K=64, half out) + fused pass1 -> S, P
    gemm_f16<128, 2, false><<<dim3(DI / 128, ROWS / 128), 256, SM128>>>(
        dtlowh, dtwh, nullptr, eh, ROWS, DI, DTR, DTR,
        dtb, Aclip, uh, S, P);
    // 5. warp-parallel carry + scan pass2
    carry_kernel<<<(BB * DI * 32) / 256, 256>>>(S, P, Cy);
    scan_pass2<<<(BB * NCH * DI / 4) / 256, 256>>>(eh, uh, xzh, Dvec, Cy, ygh);
    // 6. out_proj: out[8192,1024] = ygh * outwh^T (K=2048), f32 output
    gemm_f16<128, 0, false><<<dim3(DMOD / 128, ROWS / 128), 256, SM128>>>(
        ygh, outwh, out, nullptr, ROWS, DMOD, DI, DI,
        nullptr, nullptr, nullptr, nullptr, nullptr);
}